// round 13
// baseline (speedup 1.0000x reference)
#include <cuda_runtime.h>
#include <cuda_bf16.h>
#include <cstdint>

#define B_   4096
#define K_   1024
#define NG   4096    /* 4*H */
#define H_   1024
#define NM   4

#define STAGE_BYTES 32768     /* A 128x64 bf16 (16KB) + B 128x64 bf16 (16KB) */
#define NSTAGES     3
#define DSM_BYTES   (NSTAGES * STAGE_BYTES)   /* 96 KB -> 2 CTAs/SM */
#define CHUNKS_PER_BRANCH 16
#define TOTAL_CHUNKS      32

// ---- scratch (device globals; no runtime allocation) ----
__device__ __nv_bfloat16 g_yA[2][NM][B_][K_];   // 64 MB  bit-plane ints (bf16), K-major
__device__ __nv_bfloat16 g_Wt[2][NG][K_];       // 16 MB  weight ints, transposed [N][K]

// ======================= small math helpers =======================
__device__ __forceinline__ float pact_f(float x, float a) {
    float ax = fabsf(x);
    float t  = fabsf(ax - a);
    float s  = (x > 0.f) ? 0.5f : ((x < 0.f) ? -0.5f : 0.f);
    return s * ((ax - t) + a);
}
__device__ __forceinline__ float qr8(float x, float r) {
    float xs = x / r;
    xs = fminf(fmaxf(xs, -0.9921875f), 0.9921875f);
    return (rintf(xs * 128.f) * 0.0078125f) * r;
}
__device__ __forceinline__ float sigmoidf_fast(float x) { return 1.f / (1.f + __expf(-x)); }
// saturation-safe fast tanh: exp(2x)=inf -> 1, exp(2x)=0 -> -1
__device__ __forceinline__ float tanhf_fast(float x) {
    return 1.f - 2.f / (__expf(2.f * x) + 1.f);
}

// ======================= PTX helpers (sm_80-class only) =======================
__device__ __forceinline__ uint32_t s2u(const void* p) {
    uint32_t a;
    asm("{ .reg .u64 t; cvta.to.shared.u64 t, %1; cvt.u32.u64 %0, t; }" : "=r"(a) : "l"(p));
    return a;
}
__device__ __forceinline__ void cp16(uint32_t dst, const void* src) {
    asm volatile("cp.async.cg.shared.global [%0], [%1], 16;" :: "r"(dst), "l"(src) : "memory");
}
__device__ __forceinline__ void ldsm4(uint32_t addr, uint32_t& r0, uint32_t& r1,
                                      uint32_t& r2, uint32_t& r3) {
    asm volatile("ldmatrix.sync.aligned.m8n8.x4.shared.b16 {%0,%1,%2,%3}, [%4];"
                 : "=r"(r0), "=r"(r1), "=r"(r2), "=r"(r3) : "r"(addr));
}
__device__ __forceinline__ void hmma(float* d, const uint32_t* a, const uint32_t* b) {
    asm volatile(
        "mma.sync.aligned.m16n8k16.row.col.f32.bf16.bf16.f32 "
        "{%0,%1,%2,%3}, {%4,%5,%6,%7}, {%8,%9}, {%0,%1,%2,%3};"
        : "+f"(d[0]), "+f"(d[1]), "+f"(d[2]), "+f"(d[3])
        : "r"(a[0]), "r"(a[1]), "r"(a[2]), "r"(a[3]), "r"(b[0]), "r"(b[1]));
}

// ======================= fused prep: bit-split + weight quant/transpose ============
__global__ void prep_kernel(const float* __restrict__ input,
                            const float* __restrict__ hx,
                            const float* __restrict__ wih,
                            const float* __restrict__ whh,
                            const float* __restrict__ a1p,
                            const float* __restrict__ a11p) {
    __shared__ float tile[32][33];
    int bx  = blockIdx.x;
    int tid = threadIdx.x;
    if (bx < 8192) {
        // ---- activation bit-split ----
        int idx = bx * 256 + tid;
        int branch = idx >> 20;               // B_*K_/4 = 2^20
        int r      = idx & ((B_ * K_ / 4) - 1);
        float a = branch ? *a11p : *a1p;
        float4 x4 = ((const float4*)(branch ? hx : input))[r];
        float xs[4] = {x4.x, x4.y, x4.z, x4.w};
        unsigned short o[NM][4];
#pragma unroll
        for (int j = 0; j < 4; j++) {
            float xv = pact_f(xs[j], a) / a;
            float beta = 1.f;
#pragma unroll
            for (int mq = 0; mq < NM; mq++) {
                float s = xv / beta;
                s = fminf(fmaxf(s, -0.9921875f), 0.9921875f);
                float yi = rintf(s * 128.f);       // exact int in [-127,127]
                xv = xv - (yi * 0.0078125f) * beta;
                o[mq][j] = __bfloat16_as_ushort(__float2bfloat16(yi));
                beta *= 0.5f;
            }
        }
#pragma unroll
        for (int mq = 0; mq < NM; mq++) {
            uint2 v;
            v.x = (uint32_t)o[mq][0] | ((uint32_t)o[mq][1] << 16);
            v.y = (uint32_t)o[mq][2] | ((uint32_t)o[mq][3] << 16);
            ((uint2*)&g_yA[branch][mq][0][0])[r] = v;
        }
    } else {
        // ---- weight quant + transpose, one 32x32 tile per block ----
        int wb     = bx - 8192;               // 0..8191
        int branch = wb >> 12;                // 4096 tiles per branch
        int rem    = wb & 4095;
        int n0 = (rem & 127) * 32;
        int k0 = (rem >> 7) * 32;
        const float* w = branch ? whh : wih;
        int tx = tid & 31, ty = tid >> 5;     // 32 x 8
#pragma unroll
        for (int i = 0; i < 4; i++)
            tile[ty + i * 8][tx] = w[(size_t)(k0 + ty + i * 8) * NG + n0 + tx];
        __syncthreads();
#pragma unroll
        for (int i = 0; i < 4; i++) {
            float v = tile[tx][ty + i * 8];
            v = fminf(fmaxf(v, -0.9921875f), 0.9921875f);
            g_Wt[branch][n0 + ty + i * 8][k0 + tx] = __float2bfloat16(rintf(v * 128.f));
        }
    }
}

// ======================= bf16 HMMA GEMM + fused LSTM cell =======================
// CTA: 128 threads, tile M=128 (4 planes x 32 batch rows) x N=128 where the
// 128 N-columns are 4 GATES x 32 h-columns (B rows gate*1024 + h0 + (r&31)).
// 4 warps: warp = (mh = warp&1: 16-row half) x (nq = warp>>1: 64-col group).
// Warp holds ALL 4 planes of its 16x64 block -> plane combine in-register.
// Branch-0 combined partials stay in registers (v0). After branch-1 epilogue
// the CTA holds all 4 gates for its 32x32 (row,h) block -> smem exchange ->
// full LSTM cell math -> write new_h/new_c straight to d_out.
// 96KB dyn smem -> 2 CTAs/SM. grid = 4096 (128 blk x 32 h-blocks), swizzled.
__global__ void __launch_bounds__(128, 2) gemm_cell(
        const float* __restrict__ a1p,  const float* __restrict__ a11p,
        const float* __restrict__ bih,  const float* __restrict__ bhh,
        const float* __restrict__ cx,   float* __restrict__ out,
        const float* a3, const float* a4, const float* a5, const float* a6,
        const float* a7, const float* a8, const float* a9, const float* a10,
        const float* a11) {
    extern __shared__ __align__(128) char dsm[];
    __shared__ float sbias[2][128];

    const int tid  = threadIdx.x;
    const int lane = tid & 31;
    const int warp = tid >> 5;
    const int mh   = warp & 1;     // 16-row half of the 32 batch rows
    const int nq   = warp >> 1;    // 64-col group (0..1)

    // CTA swizzle: 16 groups of (16 blk x 16 h-blocks)
    const int g   = blockIdx.x;
    const int bg  = (g >> 8) & 7;               // blk-group 0..7
    const int ng  = g >> 11;                    // h-group 0..1
    const int rem = g & 255;
    const int blk = bg * 16 + (rem & 15);       // 0..127
    const int hb  = ng * 16 + (rem >> 4);       // 0..31
    const int h0  = hb * 32;                    // h-column base

    {
        // N-tile column nn -> global gate column (nn>>5)*1024 + h0 + (nn&31)
        int col = (tid >> 5) * H_ + h0 + (tid & 31);
        float v0b = fminf(fmaxf(bih[col], -0.9921875f), 0.9921875f);
        sbias[0][tid] = rintf(v0b * 128.f);
        float v1b = fminf(fmaxf(bhh[col], -0.9921875f), 0.9921875f);
        sbias[1][tid] = rintf(v1b * 128.f);
    }
    const float a1v  = *a1p;
    const float a11v = *a11p;

    const uint32_t smem = s2u(dsm);

    // ---- cp.async slots: 8 A + 8 B 16B-chunks per thread per stage ----
    const int row0 = tid >> 3, ch0 = tid & 7;
    const uint32_t a_src0 = (uint32_t)(((blk * 32 + row0) * K_ + ch0 * 8) * 2);
    const uint32_t a_dst0 = (uint32_t)(row0 * 128 + ((ch0 ^ (row0 & 7)) << 4));
    uint32_t b_srcs[8];
#pragma unroll
    for (int i = 0; i < 8; i++) {
        int row = row0 + 16 * i;                // B tile row 0..127
        int gcol = (row >> 5) * H_ + h0 + (row & 31);
        b_srcs[i] = (uint32_t)(((size_t)gcol * K_ + ch0 * 8) * 2);
    }
    const uint32_t b_dst0 = (uint32_t)(16384 + row0 * 128 + ((ch0 ^ (row0 & 7)) << 4));
    const char* gA = (const char*)&g_yA[0][0][0][0];
    const char* gB = (const char*)&g_Wt[0][0][0];

    // ---- ldmatrix lane constants ----
    const int m   = lane >> 3;          // matrix index within ldsm.x4
    const int rr  = lane & 7;
    const int akh = m >> 1;             // A: k-half (16B) selector
    const int bkh = m & 1;              // B: k-half selector
    uint32_t aoffx[4];                  // per plane, row-swizzle folded into bits[4:6]
#pragma unroll
    for (int p = 0; p < 4; p++) {
        int row = p * 32 + mh * 16 + (m & 1) * 8 + rr;
        aoffx[p] = (uint32_t)(row * 128) | ((uint32_t)(row & 7) << 4);
    }
    uint32_t boffx[4];
#pragma unroll
    for (int t = 0; t < 4; t++) {
        int row = nq * 64 + t * 16 + (m >> 1) * 8 + rr;
        boffx[t] = (uint32_t)(16384 + row * 128) | ((uint32_t)(row & 7) << 4);
    }

    float acc[4][8][4];                 // [plane][n8-group][frag]
#pragma unroll
    for (int p = 0; p < 4; p++)
#pragma unroll
        for (int j = 0; j < 8; j++)
#pragma unroll
            for (int d = 0; d < 4; d++) acc[p][j][d] = 0.f;

    float v0[8][4];                     // branch-0 combined partials (registers)

    auto load_stage = [&](int c, int stage) {
        int br = c >> 4;
        uint32_t k = (uint32_t)(c & 15) * 128;          // 64 bf16 = 128B per chunk
        uint32_t st = smem + (uint32_t)stage * STAGE_BYTES;
        const char* A  = gA + (size_t)br * ((size_t)NM * B_ * K_ * 2) + k;
        const char* Bp = gB + (size_t)br * ((size_t)NG * K_ * 2) + k;
#pragma unroll
        for (int i = 0; i < 8; i++) {
            cp16(st + a_dst0 + i * 2048,
                 A + a_src0 + (uint32_t)(i >> 1) * (B_ * K_ * 2)
                            + (uint32_t)(i & 1) * (16 * K_ * 2));
            cp16(st + b_dst0 + i * 2048, Bp + b_srcs[i]);
        }
    };

    auto compute_stage = [&](int stage) {
        uint32_t st = smem + (uint32_t)stage * STAGE_BYTES;
#pragma unroll
        for (int s = 0; s < 4; s++) {          // four k16 steps per BK=64
            uint32_t aks = (uint32_t)(s * 2 + akh) << 4;
            uint32_t bks = (uint32_t)(s * 2 + bkh) << 4;
            uint32_t a[4][4];
#pragma unroll
            for (int p = 0; p < 4; p++)
                ldsm4((st + aoffx[p]) ^ aks, a[p][0], a[p][1], a[p][2], a[p][3]);
#pragma unroll
            for (int t = 0; t < 4; t++) {
                uint32_t b[4];
                ldsm4((st + boffx[t]) ^ bks, b[0], b[1], b[2], b[3]);
#pragma unroll
                for (int p = 0; p < 4; p++) {
                    hmma(acc[p][2 * t],     a[p], &b[0]);
                    hmma(acc[p][2 * t + 1], a[p], &b[2]);
                }
            }
        }
    };

    // branch 0: plane combine in-register -> keep in v0
    auto epilogue0 = [&]() {
        float sc0 = a1v * 0.0078125f;
#pragma unroll
        for (int j = 0; j < 8; j++) {
#pragma unroll
            for (int d = 0; d < 4; d++) {
                int nn = nq * 64 + j * 8 + (lane & 3) * 2 + (d & 1);
                float bz = sbias[0][nn];
                float v = 0.f;
#pragma unroll
                for (int p = 0; p < 4; p++) {
                    float t = acc[p][j][d] * 0.0078125f + bz;
                    float q = fminf(fmaxf(rintf(t), -127.f), 127.f);
                    v += q * (sc0 / (float)(1 << p));
                }
                v0[j][d] = v;
            }
        }
    };

    // ---- pipeline: 3 stages, 32 chunks (branch = chunk>>4) ----
#pragma unroll
    for (int c = 0; c < NSTAGES - 1; c++) {
        load_stage(c, c);
        asm volatile("cp.async.commit_group;" ::: "memory");
    }
    int ls = NSTAGES - 1;
    int cs = 0;
    for (int c = 0; c < TOTAL_CHUNKS; c++) {
        asm volatile("cp.async.wait_group %0;" :: "n"(NSTAGES - 2) : "memory");
        __syncthreads();
        if (c + NSTAGES - 1 < TOTAL_CHUNKS) load_stage(c + NSTAGES - 1, ls);
        asm volatile("cp.async.commit_group;" ::: "memory");
        if (++ls == NSTAGES) ls = 0;
        compute_stage(cs);
        if (++cs == NSTAGES) cs = 0;
        if (c == CHUNKS_PER_BRANCH - 1) {
            epilogue0();
#pragma unroll
            for (int p = 0; p < 4; p++)
#pragma unroll
                for (int j = 0; j < 8; j++)
#pragma unroll
                    for (int d = 0; d < 4; d++) acc[p][j][d] = 0.f;
        }
    }

    // branch 1: combine + add v0 -> stage full gate tile in smem
    __syncthreads();                       // all warps done with stage smem
    float* comb = (float*)dsm;             // [32][132]
    {
        float sc0 = a11v * 0.0078125f;
#pragma unroll
        for (int j = 0; j < 8; j++) {
#pragma unroll
            for (int d = 0; d < 4; d++) {
                int nn = nq * 64 + j * 8 + (lane & 3) * 2 + (d & 1);
                int rw = mh * 16 + (lane >> 2) + (d >> 1) * 8;
                float bz = sbias[1][nn];
                float v = v0[j][d];
#pragma unroll
                for (int p = 0; p < 4; p++) {
                    float t = acc[p][j][d] * 0.0078125f + bz;
                    float q = fminf(fmaxf(rintf(t), -127.f), 127.f);
                    v += q * (sc0 / (float)(1 << p));
                }
                comb[rw * 132 + nn] = v;
            }
        }
    }
    __syncthreads();

    // ---- fused LSTM cell: 32 rows x 32 h-cols, 8 elements/thread ----
    {
        float v3 = *a3, v4 = *a4, v5 = *a5, v6 = *a6, v7 = *a7;
        float v8 = *a8, v9 = *a9, v10 = *a10, v11v = *a11;
        int hh = tid & 31;
        int r0 = tid >> 5;                 // 0..3
#pragma unroll
        for (int ri = 0; ri < 8; ri++) {
            int r = r0 * 8 + ri;           // 0..31
            float gi = comb[r * 132 + hh];
            float gj = comb[r * 132 + 32 + hh];
            float gf = comb[r * 132 + 64 + hh];
            float go = comb[r * 132 + 96 + hh];
            int gidx = (blk * 32 + r) * H_ + h0 + hh;
            float cxv = cx[gidx];

            float fg  = qr8(pact_f(sigmoidf_fast(gf), v3), v3);
            float ig  = qr8(pact_f(sigmoidf_fast(gi), v4), v4);
            float act = qr8(pact_f(tanhf_fast(gj),    v5), v5);
            float og  = qr8(pact_f(sigmoidf_fast(go), v6), v6);
            float gc  = qr8(pact_f(cxv * fg,  v7), v7);
            float ai  = qr8(pact_f(ig * act,  v8), v8);
            float nc  = qr8(pact_f(gc + ai,   v9), v9);
            float ac  = qr8(pact_f(tanhf_fast(nc), v10), v10);
            float nh  = qr8(pact_f(ac * og, v11v), v11v);

            out[gidx]           = nh;
            out[B_ * H_ + gidx] = nc;
        }
    }
}

// ======================= launch =======================
extern "C" void kernel_launch(void* const* d_in, const int* in_sizes, int n_in,
                              void* d_out, int out_size) {
    const float* input = (const float*)d_in[0];
    const float* hx    = (const float*)d_in[1];
    const float* cx    = (const float*)d_in[2];
    const float* wih   = (const float*)d_in[3];
    const float* whh   = (const float*)d_in[4];
    const float* bih   = (const float*)d_in[5];
    const float* bhh   = (const float*)d_in[6];
    const float* a1    = (const float*)d_in[7];
    const float* a3    = (const float*)d_in[8];
    const float* a4    = (const float*)d_in[9];
    const float* a5    = (const float*)d_in[10];
    const float* a6    = (const float*)d_in[11];
    const float* a7    = (const float*)d_in[12];
    const float* a8    = (const float*)d_in[13];
    const float* a9    = (const float*)d_in[14];
    const float* a10   = (const float*)d_in[15];
    const float* a11   = (const float*)d_in[16];
    float* out = (float*)d_out;

    static int configured = 0;
    if (!configured) {
        cudaFuncSetAttribute(gemm_cell, cudaFuncAttributeMaxDynamicSharedMemorySize,
                             DSM_BYTES);
        configured = 1;
    }

    prep_kernel<<<16384, 256>>>(input, hx, wih, whh, a1, a11);

    gemm_cell<<<4096, 128, DSM_BYTES>>>(a1, a11, bih, bhh, cx, out,
                                        a3, a4, a5, a6, a7, a8, a9, a10, a11);
}

// round 14
// speedup vs baseline: 1.5499x; 1.5499x over previous
#include <cuda_runtime.h>
#include <cuda_bf16.h>
#include <cstdint>

#define B_   4096
#define K_   1024
#define NG   4096    /* 4*H */
#define H_   1024
#define NM   4

#define STAGE_BYTES 32768     /* A 128x64 bf16 (16KB) + B 128x64 bf16 (16KB) */
#define NSTAGES     3
#define DSM_BYTES   (NSTAGES * STAGE_BYTES)   /* 96 KB -> 2 CTAs/SM */
#define CHUNKS_PER_BRANCH 16
#define TOTAL_CHUNKS      32

// ---- scratch (device globals; no runtime allocation) ----
__device__ __nv_bfloat16 g_yA[2][NM][B_][K_];   // 64 MB  bit-plane ints (bf16), K-major
// weights transposed AND gate-interleaved: row (h*4 + gate) holds W[:, gate*H + h]
__device__ __nv_bfloat16 g_Wt2[2][NG][K_];      // 16 MB

// ======================= small math helpers =======================
__device__ __forceinline__ float pact_f(float x, float a) {
    float ax = fabsf(x);
    float t  = fabsf(ax - a);
    float s  = (x > 0.f) ? 0.5f : ((x < 0.f) ? -0.5f : 0.f);
    return s * ((ax - t) + a);
}
__device__ __forceinline__ float qr8(float x, float r) {
    float xs = x / r;
    xs = fminf(fmaxf(xs, -0.9921875f), 0.9921875f);
    return (rintf(xs * 128.f) * 0.0078125f) * r;
}
__device__ __forceinline__ float sigmoidf_fast(float x) { return 1.f / (1.f + __expf(-x)); }
__device__ __forceinline__ float tanhf_fast(float x) {
    return 1.f - 2.f / (__expf(2.f * x) + 1.f);
}

// ======================= PTX helpers (sm_80-class only) =======================
__device__ __forceinline__ uint32_t s2u(const void* p) {
    uint32_t a;
    asm("{ .reg .u64 t; cvta.to.shared.u64 t, %1; cvt.u32.u64 %0, t; }" : "=r"(a) : "l"(p));
    return a;
}
__device__ __forceinline__ void cp16(uint32_t dst, const void* src) {
    asm volatile("cp.async.cg.shared.global [%0], [%1], 16;" :: "r"(dst), "l"(src) : "memory");
}
__device__ __forceinline__ void ldsm4(uint32_t addr, uint32_t& r0, uint32_t& r1,
                                      uint32_t& r2, uint32_t& r3) {
    asm volatile("ldmatrix.sync.aligned.m8n8.x4.shared.b16 {%0,%1,%2,%3}, [%4];"
                 : "=r"(r0), "=r"(r1), "=r"(r2), "=r"(r3) : "r"(addr));
}
__device__ __forceinline__ void hmma(float* d, const uint32_t* a, const uint32_t* b) {
    asm volatile(
        "mma.sync.aligned.m16n8k16.row.col.f32.bf16.bf16.f32 "
        "{%0,%1,%2,%3}, {%4,%5,%6,%7}, {%8,%9}, {%0,%1,%2,%3};"
        : "+f"(d[0]), "+f"(d[1]), "+f"(d[2]), "+f"(d[3])
        : "r"(a[0]), "r"(a[1]), "r"(a[2]), "r"(a[3]), "r"(b[0]), "r"(b[1]));
}

// ======================= fused prep: bit-split + weight quant/transpose ============
__global__ void prep_kernel(const float* __restrict__ input,
                            const float* __restrict__ hx,
                            const float* __restrict__ wih,
                            const float* __restrict__ whh,
                            const float* __restrict__ a1p,
                            const float* __restrict__ a11p) {
    __shared__ float tile[32][33];
    int bx  = blockIdx.x;
    int tid = threadIdx.x;
    if (bx < 8192) {
        // ---- activation bit-split ----
        int idx = bx * 256 + tid;
        int branch = idx >> 20;               // B_*K_/4 = 2^20
        int r      = idx & ((B_ * K_ / 4) - 1);
        float a = branch ? *a11p : *a1p;
        float4 x4 = ((const float4*)(branch ? hx : input))[r];
        float xs[4] = {x4.x, x4.y, x4.z, x4.w};
        unsigned short o[NM][4];
#pragma unroll
        for (int j = 0; j < 4; j++) {
            float xv = pact_f(xs[j], a) / a;
            float beta = 1.f;
#pragma unroll
            for (int mq = 0; mq < NM; mq++) {
                float s = xv / beta;
                s = fminf(fmaxf(s, -0.9921875f), 0.9921875f);
                float yi = rintf(s * 128.f);       // exact int in [-127,127]
                xv = xv - (yi * 0.0078125f) * beta;
                o[mq][j] = __bfloat16_as_ushort(__float2bfloat16(yi));
                beta *= 0.5f;
            }
        }
#pragma unroll
        for (int mq = 0; mq < NM; mq++) {
            uint2 v;
            v.x = (uint32_t)o[mq][0] | ((uint32_t)o[mq][1] << 16);
            v.y = (uint32_t)o[mq][2] | ((uint32_t)o[mq][3] << 16);
            ((uint2*)&g_yA[branch][mq][0][0])[r] = v;
        }
    } else {
        // ---- weight quant + transpose + gate-interleave, one 32x32 tile per block ----
        int wb     = bx - 8192;               // 0..8191
        int branch = wb >> 12;                // 4096 tiles per branch
        int rem    = wb & 4095;
        int n0 = (rem & 127) * 32;
        int k0 = (rem >> 7) * 32;
        const float* w = branch ? whh : wih;
        int tx = tid & 31, ty = tid >> 5;     // 32 x 8
#pragma unroll
        for (int i = 0; i < 4; i++)
            tile[ty + i * 8][tx] = w[(size_t)(k0 + ty + i * 8) * NG + n0 + tx];
        __syncthreads();
#pragma unroll
        for (int i = 0; i < 4; i++) {
            float v = tile[tx][ty + i * 8];
            v = fminf(fmaxf(v, -0.9921875f), 0.9921875f);
            int n = n0 + ty + i * 8;          // global gate-col
            int row = (n & (H_ - 1)) * 4 + (n >> 10);   // h*4 + gate
            g_Wt2[branch][row][k0 + tx] = __float2bfloat16(rintf(v * 128.f));
        }
    }
}

// ======================= bf16 HMMA GEMM + fused LSTM cell =======================
// CTA: 128 threads, tile M=128 (4 planes x 32 batch rows) x N=128 where the
// 128 N-columns are 128 CONTIGUOUS g_Wt2 rows = 32 h-cols x 4 gates interleaved.
// Mainloop byte-identical to the R10 champion (single b_src0, immediate strides).
// 4 warps: warp = (mh = warp&1) x (nq = warp>>1). All 4 planes per warp;
// branch-0 partials kept in registers (v0). After branch-1 epilogue the CTA
// holds i,j,f,o for its 32x32 (row,h) block -> smem exchange -> LSTM cell ->
// new_h/new_c straight to d_out. 96KB dsm -> 2 CTAs/SM. grid=4096 swizzled.
__global__ void __launch_bounds__(128, 2) gemm_cell(
        const float* __restrict__ a1p,  const float* __restrict__ a11p,
        const float* __restrict__ bih,  const float* __restrict__ bhh,
        const float* __restrict__ cx,   float* __restrict__ out,
        const float* a3, const float* a4, const float* a5, const float* a6,
        const float* a7, const float* a8, const float* a9, const float* a10,
        const float* a11) {
    extern __shared__ __align__(128) char dsm[];
    __shared__ float sbias[2][128];

    const int tid  = threadIdx.x;
    const int lane = tid & 31;
    const int warp = tid >> 5;
    const int mh   = warp & 1;     // 16-row half of the 32 batch rows
    const int nq   = warp >> 1;    // 64-col group (0..1)

    // CTA swizzle: 16 groups of (16 blk x 16 h-blocks)
    const int g   = blockIdx.x;
    const int bg  = (g >> 8) & 7;               // blk-group 0..7
    const int ng  = g >> 11;                    // h-group 0..1
    const int rem = g & 255;
    const int blk = bg * 16 + (rem & 15);       // 0..127
    const int hb  = ng * 16 + (rem >> 4);       // 0..31
    const int h0  = hb * 32;                    // h-column base
    const int n0  = hb * 128;                   // g_Wt2 row base

    {
        // tile column nn -> global gate col (nn&3)*H + h0 + (nn>>2)
        int col = (tid & 3) * H_ + h0 + (tid >> 2);
        float v0b = fminf(fmaxf(bih[col], -0.9921875f), 0.9921875f);
        sbias[0][tid] = rintf(v0b * 128.f);
        float v1b = fminf(fmaxf(bhh[col], -0.9921875f), 0.9921875f);
        sbias[1][tid] = rintf(v1b * 128.f);
    }
    const float a1v  = *a1p;
    const float a11v = *a11p;

    const uint32_t smem = s2u(dsm);

    // ---- cp.async slots: 8 A + 8 B 16B-chunks per thread per stage ----
    const int row0 = tid >> 3, ch0 = tid & 7;
    const uint32_t a_src0 = (uint32_t)(((blk * 32 + row0) * K_ + ch0 * 8) * 2);
    const uint32_t a_dst0 = (uint32_t)(row0 * 128 + ((ch0 ^ (row0 & 7)) << 4));
    const uint32_t b_src0 = (uint32_t)(((n0 + row0) * K_ + ch0 * 8) * 2);
    const uint32_t b_dst0 = (uint32_t)(16384 + row0 * 128 + ((ch0 ^ (row0 & 7)) << 4));
    const char* gA = (const char*)&g_yA[0][0][0][0];
    const char* gB = (const char*)&g_Wt2[0][0][0];

    // ---- ldmatrix lane constants ----
    const int m   = lane >> 3;
    const int rr  = lane & 7;
    const int akh = m >> 1;             // A: k-half (16B) selector
    const int bkh = m & 1;              // B: k-half selector
    uint32_t aoffx[4];
#pragma unroll
    for (int p = 0; p < 4; p++) {
        int row = p * 32 + mh * 16 + (m & 1) * 8 + rr;
        aoffx[p] = (uint32_t)(row * 128) | ((uint32_t)(row & 7) << 4);
    }
    uint32_t boffx[4];
#pragma unroll
    for (int t = 0; t < 4; t++) {
        int row = nq * 64 + t * 16 + (m >> 1) * 8 + rr;
        boffx[t] = (uint32_t)(16384 + row * 128) | ((uint32_t)(row & 7) << 4);
    }

    float acc[4][8][4];                 // [plane][n8-group][frag]
#pragma unroll
    for (int p = 0; p < 4; p++)
#pragma unroll
        for (int j = 0; j < 8; j++)
#pragma unroll
            for (int d = 0; d < 4; d++) acc[p][j][d] = 0.f;

    float v0[8][4];                     // branch-0 combined partials (registers)

    auto load_stage = [&](int c, int stage) {
        int br = c >> 4;
        uint32_t k = (uint32_t)(c & 15) * 128;
        uint32_t st = smem + (uint32_t)stage * STAGE_BYTES;
        const char* A  = gA + (size_t)br * ((size_t)NM * B_ * K_ * 2) + k;
        const char* Bp = gB + (size_t)br * ((size_t)NG * K_ * 2) + k;
#pragma unroll
        for (int i = 0; i < 8; i++) {
            cp16(st + a_dst0 + i * 2048,
                 A + a_src0 + (uint32_t)(i >> 1) * (B_ * K_ * 2)
                            + (uint32_t)(i & 1) * (16 * K_ * 2));
            cp16(st + b_dst0 + i * 2048, Bp + b_src0 + (uint32_t)i * (16 * K_ * 2));
        }
    };

    auto compute_stage = [&](int stage) {
        uint32_t st = smem + (uint32_t)stage * STAGE_BYTES;
#pragma unroll
        for (int s = 0; s < 4; s++) {
            uint32_t aks = (uint32_t)(s * 2 + akh) << 4;
            uint32_t bks = (uint32_t)(s * 2 + bkh) << 4;
            uint32_t a[4][4];
#pragma unroll
            for (int p = 0; p < 4; p++)
                ldsm4((st + aoffx[p]) ^ aks, a[p][0], a[p][1], a[p][2], a[p][3]);
#pragma unroll
            for (int t = 0; t < 4; t++) {
                uint32_t b[4];
                ldsm4((st + boffx[t]) ^ bks, b[0], b[1], b[2], b[3]);
#pragma unroll
                for (int p = 0; p < 4; p++) {
                    hmma(acc[p][2 * t],     a[p], &b[0]);
                    hmma(acc[p][2 * t + 1], a[p], &b[2]);
                }
            }
        }
    };

    // branch 0: plane combine in-register -> keep in v0
    auto epilogue0 = [&]() {
        float sc0 = a1v * 0.0078125f;
#pragma unroll
        for (int j = 0; j < 8; j++) {
#pragma unroll
            for (int d = 0; d < 4; d++) {
                int nn = nq * 64 + j * 8 + (lane & 3) * 2 + (d & 1);
                float bz = sbias[0][nn];
                float v = 0.f;
#pragma unroll
                for (int p = 0; p < 4; p++) {
                    float t = acc[p][j][d] * 0.0078125f + bz;
                    float q = fminf(fmaxf(rintf(t), -127.f), 127.f);
                    v += q * (sc0 / (float)(1 << p));
                }
                v0[j][d] = v;
            }
        }
    };

    // ---- pipeline: 3 stages, 32 chunks (branch = chunk>>4) ----
#pragma unroll
    for (int c = 0; c < NSTAGES - 1; c++) {
        load_stage(c, c);
        asm volatile("cp.async.commit_group;" ::: "memory");
    }
    int ls = NSTAGES - 1;
    int cs = 0;
    for (int c = 0; c < TOTAL_CHUNKS; c++) {
        asm volatile("cp.async.wait_group %0;" :: "n"(NSTAGES - 2) : "memory");
        __syncthreads();
        if (c + NSTAGES - 1 < TOTAL_CHUNKS) load_stage(c + NSTAGES - 1, ls);
        asm volatile("cp.async.commit_group;" ::: "memory");
        if (++ls == NSTAGES) ls = 0;
        compute_stage(cs);
        if (++cs == NSTAGES) cs = 0;
        if (c == CHUNKS_PER_BRANCH - 1) {
            epilogue0();
#pragma unroll
            for (int p = 0; p < 4; p++)
#pragma unroll
                for (int j = 0; j < 8; j++)
#pragma unroll
                    for (int d = 0; d < 4; d++) acc[p][j][d] = 0.f;
        }
    }

    // branch 1: combine + add v0 -> stage gate tile in smem
    __syncthreads();
    float* comb = (float*)dsm;             // [32][132]
    {
        float sc0 = a11v * 0.0078125f;
#pragma unroll
        for (int j = 0; j < 8; j++) {
#pragma unroll
            for (int d = 0; d < 4; d++) {
                int nn = nq * 64 + j * 8 + (lane & 3) * 2 + (d & 1);
                int rw = mh * 16 + (lane >> 2) + (d >> 1) * 8;
                float bz = sbias[1][nn];
                float v = v0[j][d];
#pragma unroll
                for (int p = 0; p < 4; p++) {
                    float t = acc[p][j][d] * 0.0078125f + bz;
                    float q = fminf(fmaxf(rintf(t), -127.f), 127.f);
                    v += q * (sc0 / (float)(1 << p));
                }
                comb[rw * 132 + nn] = v;
            }
        }
    }
    __syncthreads();

    // ---- fused LSTM cell: 32 rows x 32 h-cols, 8 elements/thread ----
    {
        float v3 = *a3, v4 = *a4, v5 = *a5, v6 = *a6, v7 = *a7;
        float v8 = *a8, v9 = *a9, v10 = *a10, v11v = *a11;
        int hh = tid & 31;
        int r0 = tid >> 5;                 // 0..3 (== warp; lanes = hh)
#pragma unroll
        for (int ri = 0; ri < 8; ri++) {
            int r = r0 * 8 + ri;           // 0..31
            // tile col nn = 4*hh + gate (gates interleaved)
            float gi = comb[r * 132 + 4 * hh + 0];
            float gj = comb[r * 132 + 4 * hh + 1];
            float gf = comb[r * 132 + 4 * hh + 2];
            float go = comb[r * 132 + 4 * hh + 3];
            int gidx = (blk * 32 + r) * H_ + h0 + hh;
            float cxv = cx[gidx];

            float fg  = qr8(pact_f(sigmoidf_fast(gf), v3), v3);
            float ig  = qr8(pact_f(sigmoidf_fast(gi), v4), v4);
            float act = qr8(pact_f(tanhf_fast(gj),    v5), v5);
            float og  = qr8(pact_f(sigmoidf_fast(go), v6), v6);
            float gc  = qr8(pact_f(cxv * fg,  v7), v7);
            float ai  = qr8(pact_f(ig * act,  v8), v8);
            float nc  = qr8(pact_f(gc + ai,   v9), v9);
            float tc  = qr8(pact_f(tanhf_fast(nc), v10), v10);
            float nh  = qr8(pact_f(tc * og, v11v), v11v);

            out[gidx]           = nh;
            out[B_ * H_ + gidx] = nc;
        }
    }
}

// ======================= launch =======================
extern "C" void kernel_launch(void* const* d_in, const int* in_sizes, int n_in,
                              void* d_out, int out_size) {
    const float* input = (const float*)d_in[0];
    const float* hx    = (const float*)d_in[1];
    const float* cx    = (const float*)d_in[2];
    const float* wih   = (const float*)d_in[3];
    const float* whh   = (const float*)d_in[4];
    const float* bih   = (const float*)d_in[5];
    const float* bhh   = (const float*)d_in[6];
    const float* a1    = (const float*)d_in[7];
    const float* a3    = (const float*)d_in[8];
    const float* a4    = (const float*)d_in[9];
    const float* a5    = (const float*)d_in[10];
    const float* a6    = (const float*)d_in[11];
    const float* a7    = (const float*)d_in[12];
    const float* a8    = (const float*)d_in[13];
    const float* a9    = (const float*)d_in[14];
    const float* a10   = (const float*)d_in[15];
    const float* a11   = (const float*)d_in[16];
    float* out = (float*)d_out;

    static int configured = 0;
    if (!configured) {
        cudaFuncSetAttribute(gemm_cell, cudaFuncAttributeMaxDynamicSharedMemorySize,
                             DSM_BYTES);
        configured = 1;
    }

    prep_kernel<<<16384, 256>>>(input, hx, wih, whh, a1, a11);

    gemm_cell<<<4096, 128, DSM_BYTES>>>(a1, a11, bih, bhh, cx, out,
                                        a3, a4, a5, a6, a7, a8, a9, a10, a11);
}

// round 15
// speedup vs baseline: 1.6793x; 1.0835x over previous
#include <cuda_runtime.h>
#include <cuda_bf16.h>
#include <cstdint>

#define B_   4096
#define K_   1024
#define NG   4096    /* 4*H */
#define H_   1024
#define NM   4

#define STAGE_BYTES 24576     /* A 128x64 bf16 (16KB) + B 64x64 bf16 (8KB) */
#define NSTAGES     3
#define DSM_BYTES   (NSTAGES * STAGE_BYTES)   /* 72 KB -> 3 CTAs/SM */
#define CHUNKS_PER_BRANCH 16
#define TOTAL_CHUNKS      32

// ---- scratch (device globals; no runtime allocation) ----
__device__ __nv_bfloat16 g_yA[2][NM][B_][K_];   // 64 MB  bit-plane ints (bf16), K-major
__device__ __nv_bfloat16 g_Wt[2][NG][K_];       // 16 MB  weight ints, transposed [N][K]
__device__ float         g_part[B_][NG];        // 64 MB  final gates

// ======================= small math helpers =======================
__device__ __forceinline__ float pact_f(float x, float a) {
    float ax = fabsf(x);
    float t  = fabsf(ax - a);
    float s  = (x > 0.f) ? 0.5f : ((x < 0.f) ? -0.5f : 0.f);
    return s * ((ax - t) + a);
}
__device__ __forceinline__ float qr8(float x, float r) {
    float xs = x / r;
    xs = fminf(fmaxf(xs, -0.9921875f), 0.9921875f);
    return (rintf(xs * 128.f) * 0.0078125f) * r;
}
__device__ __forceinline__ float sigmoidf_fast(float x) { return 1.f / (1.f + __expf(-x)); }
__device__ __forceinline__ float tanhf_fast(float x) {
    return 1.f - 2.f / (__expf(2.f * x) + 1.f);
}

// ======================= PTX helpers (sm_80-class only) =======================
__device__ __forceinline__ uint32_t s2u(const void* p) {
    uint32_t a;
    asm("{ .reg .u64 t; cvta.to.shared.u64 t, %1; cvt.u32.u64 %0, t; }" : "=r"(a) : "l"(p));
    return a;
}
__device__ __forceinline__ void cp16(uint32_t dst, const void* src) {
    asm volatile("cp.async.cg.shared.global [%0], [%1], 16;" :: "r"(dst), "l"(src) : "memory");
}
__device__ __forceinline__ void ldsm4(uint32_t addr, uint32_t& r0, uint32_t& r1,
                                      uint32_t& r2, uint32_t& r3) {
    asm volatile("ldmatrix.sync.aligned.m8n8.x4.shared.b16 {%0,%1,%2,%3}, [%4];"
                 : "=r"(r0), "=r"(r1), "=r"(r2), "=r"(r3) : "r"(addr));
}
__device__ __forceinline__ void hmma(float* d, const uint32_t* a, const uint32_t* b) {
    asm volatile(
        "mma.sync.aligned.m16n8k16.row.col.f32.bf16.bf16.f32 "
        "{%0,%1,%2,%3}, {%4,%5,%6,%7}, {%8,%9}, {%0,%1,%2,%3};"
        : "+f"(d[0]), "+f"(d[1]), "+f"(d[2]), "+f"(d[3])
        : "r"(a[0]), "r"(a[1]), "r"(a[2]), "r"(a[3]), "r"(b[0]), "r"(b[1]));
}

// ======================= fused prep: bit-split + weight quant/transpose ============
__global__ void prep_kernel(const float* __restrict__ input,
                            const float* __restrict__ hx,
                            const float* __restrict__ wih,
                            const float* __restrict__ whh,
                            const float* __restrict__ a1p,
                            const float* __restrict__ a11p) {
    __shared__ float tile[32][33];
    int bx  = blockIdx.x;
    int tid = threadIdx.x;
    if (bx < 8192) {
        // ---- activation bit-split ----
        int idx = bx * 256 + tid;
        int branch = idx >> 20;               // B_*K_/4 = 2^20
        int r      = idx & ((B_ * K_ / 4) - 1);
        float a = branch ? *a11p : *a1p;
        float4 x4 = ((const float4*)(branch ? hx : input))[r];
        float xs[4] = {x4.x, x4.y, x4.z, x4.w};
        unsigned short o[NM][4];
#pragma unroll
        for (int j = 0; j < 4; j++) {
            float xv = pact_f(xs[j], a) / a;
            float beta = 1.f;
#pragma unroll
            for (int mq = 0; mq < NM; mq++) {
                float s = xv / beta;
                s = fminf(fmaxf(s, -0.9921875f), 0.9921875f);
                float yi = rintf(s * 128.f);       // exact int in [-127,127]
                xv = xv - (yi * 0.0078125f) * beta;
                o[mq][j] = __bfloat16_as_ushort(__float2bfloat16(yi));
                beta *= 0.5f;
            }
        }
#pragma unroll
        for (int mq = 0; mq < NM; mq++) {
            uint2 v;
            v.x = (uint32_t)o[mq][0] | ((uint32_t)o[mq][1] << 16);
            v.y = (uint32_t)o[mq][2] | ((uint32_t)o[mq][3] << 16);
            ((uint2*)&g_yA[branch][mq][0][0])[r] = v;
        }
    } else {
        // ---- weight quant + transpose, one 32x32 tile per block ----
        int wb     = bx - 8192;               // 0..8191
        int branch = wb >> 12;                // 4096 tiles per branch
        int rem    = wb & 4095;
        int n0 = (rem & 127) * 32;
        int k0 = (rem >> 7) * 32;
        const float* w = branch ? whh : wih;
        int tx = tid & 31, ty = tid >> 5;     // 32 x 8
#pragma unroll
        for (int i = 0; i < 4; i++)
            tile[ty + i * 8][tx] = w[(size_t)(k0 + ty + i * 8) * NG + n0 + tx];
        __syncthreads();
#pragma unroll
        for (int i = 0; i < 4; i++) {
            float v = tile[tx][ty + i * 8];
            v = fminf(fmaxf(v, -0.9921875f), 0.9921875f);
            g_Wt[branch][n0 + ty + i * 8][k0 + tx] = __float2bfloat16(rintf(v * 128.f));
        }
    }
}

// ======================= bf16 HMMA GEMM, both branches fused =======================
// CTA: 128 threads, tile M=128 (4 planes x 32 batch rows) x N=64. BK=64.
// 4 warps: warp = (mh = warp&1: 16-row half) x (nq = warp>>1: 32-col group).
// Warp tile 16x32 x 4 planes -> acc 64 regs -> ~145 regs total, fits the
// 170-reg cap at 3 CTAs/SM. 72KB dyn smem x3 = 216KB -> 3 CTAs/SM (6 warps/SMSP
// across CTAs) WITH full 3-stage prefetch depth (unlike R11's 2-stage).
// grid = 8192 (128 blk x 64 n-blocks), swizzled 16x16 groups for L2 reuse.
__global__ void __launch_bounds__(128, 3) gemm_bf16(const float* __restrict__ a1p,
                                                    const float* __restrict__ a11p,
                                                    const float* __restrict__ bih,
                                                    const float* __restrict__ bhh) {
    extern __shared__ __align__(128) char dsm[];
    __shared__ float sbias[2][64];

    const int tid  = threadIdx.x;
    const int lane = tid & 31;
    const int warp = tid >> 5;
    const int mh   = warp & 1;     // 16-row half of the 32 batch rows
    const int nq   = warp >> 1;    // 32-col group (0..1)

    // CTA swizzle: 32 groups of (16 blk x 16 n-blocks)
    const int g   = blockIdx.x;
    const int bg  = (g >> 8) & 7;               // blk-group 0..7
    const int ng  = g >> 11;                    // n-group 0..3
    const int rem = g & 255;
    const int blk = bg * 16 + (rem & 15);       // 0..127
    const int n0  = (ng * 16 + (rem >> 4)) * 64;   // 0..4032

    if (tid < 64) {
        float v0b = fminf(fmaxf(bih[n0 + tid], -0.9921875f), 0.9921875f);
        sbias[0][tid] = rintf(v0b * 128.f);
        float v1b = fminf(fmaxf(bhh[n0 + tid], -0.9921875f), 0.9921875f);
        sbias[1][tid] = rintf(v1b * 128.f);
    }
    const float a1v  = *a1p;
    const float a11v = *a11p;

    const uint32_t smem = s2u(dsm);

    // ---- cp.async slots: 8 A + 4 B 16B-chunks per thread per stage ----
    // rows are 128B = 8 chunks; swizzle: chunk' = chunk ^ (row&7)
    const int row0 = tid >> 3, ch0 = tid & 7;   // row0: 0..15
    const uint32_t a_src0 = (uint32_t)(((blk * 32 + row0) * K_ + ch0 * 8) * 2);
    const uint32_t a_dst0 = (uint32_t)(row0 * 128 + ((ch0 ^ (row0 & 7)) << 4));
    const uint32_t b_src0 = (uint32_t)(((n0 + row0) * K_ + ch0 * 8) * 2);
    const uint32_t b_dst0 = (uint32_t)(16384 + row0 * 128 + ((ch0 ^ (row0 & 7)) << 4));
    const char* gA = (const char*)&g_yA[0][0][0][0];
    const char* gB = (const char*)&g_Wt[0][0][0];

    // ---- ldmatrix lane constants ----
    const int m   = lane >> 3;          // matrix index within ldsm.x4
    const int rr  = lane & 7;
    const int akh = m >> 1;             // A: k-half (16B) selector
    const int bkh = m & 1;              // B: k-half selector
    uint32_t aoffx[4];                  // per plane, row-swizzle folded into bits[4:6]
#pragma unroll
    for (int p = 0; p < 4; p++) {
        int row = p * 32 + mh * 16 + (m & 1) * 8 + rr;
        aoffx[p] = (uint32_t)(row * 128) | ((uint32_t)(row & 7) << 4);
    }
    uint32_t boffx[2];
#pragma unroll
    for (int t = 0; t < 2; t++) {
        int row = nq * 32 + t * 16 + (m >> 1) * 8 + rr;
        boffx[t] = (uint32_t)(16384 + row * 128) | ((uint32_t)(row & 7) << 4);
    }

    float acc[4][4][4];                 // [plane][n8-group][frag]
#pragma unroll
    for (int p = 0; p < 4; p++)
#pragma unroll
        for (int j = 0; j < 4; j++)
#pragma unroll
            for (int d = 0; d < 4; d++) acc[p][j][d] = 0.f;

    auto load_stage = [&](int c, int stage) {
        int br = c >> 4;
        uint32_t k = (uint32_t)(c & 15) * 128;          // 64 bf16 = 128B per chunk
        uint32_t st = smem + (uint32_t)stage * STAGE_BYTES;
        const char* A  = gA + (size_t)br * ((size_t)NM * B_ * K_ * 2) + k;
        const char* Bp = gB + (size_t)br * ((size_t)NG * K_ * 2) + k;
#pragma unroll
        for (int i = 0; i < 8; i++) {
            cp16(st + a_dst0 + i * 2048,
                 A + a_src0 + (uint32_t)(i >> 1) * (B_ * K_ * 2)
                            + (uint32_t)(i & 1) * (16 * K_ * 2));
        }
#pragma unroll
        for (int i = 0; i < 4; i++)
            cp16(st + b_dst0 + i * 2048, Bp + b_src0 + (uint32_t)i * (16 * K_ * 2));
    };

    auto compute_stage = [&](int stage) {
        uint32_t st = smem + (uint32_t)stage * STAGE_BYTES;
#pragma unroll
        for (int s = 0; s < 4; s++) {          // four k16 steps per BK=64
            uint32_t aks = (uint32_t)(s * 2 + akh) << 4;
            uint32_t bks = (uint32_t)(s * 2 + bkh) << 4;
            uint32_t a[4][4];
#pragma unroll
            for (int p = 0; p < 4; p++)
                ldsm4((st + aoffx[p]) ^ aks, a[p][0], a[p][1], a[p][2], a[p][3]);
#pragma unroll
            for (int t = 0; t < 2; t++) {
                uint32_t b[4];
                ldsm4((st + boffx[t]) ^ bks, b[0], b[1], b[2], b[3]);
#pragma unroll
                for (int p = 0; p < 4; p++) {
                    hmma(acc[p][2 * t],     a[p], &b[0]);
                    hmma(acc[p][2 * t + 1], a[p], &b[2]);
                }
            }
        }
    };

    // plane combine fully in-register -> direct global store/accumulate
    auto epilogue = [&](int br) {
        float av = br ? a11v : a1v;
        float sc0 = av * 0.0078125f;
#pragma unroll
        for (int j = 0; j < 4; j++) {
            int nnb = nq * 32 + j * 8 + (lane & 3) * 2;
#pragma unroll
            for (int d = 0; d < 4; d++) {
                int nn = nnb + (d & 1);
                int rw = mh * 16 + (lane >> 2) + (d >> 1) * 8;
                float bz = sbias[br][nn];
                float v = 0.f;
#pragma unroll
                for (int p = 0; p < 4; p++) {
                    float t = acc[p][j][d] * 0.0078125f + bz;
                    float q = fminf(fmaxf(rintf(t), -127.f), 127.f);
                    v += q * (sc0 / (float)(1 << p));
                }
                float* dst = &g_part[blk * 32 + rw][n0 + nn];
                if (br == 0) *dst = v; else *dst += v;
            }
        }
    };

    // ---- pipeline: 3 stages, 32 chunks (branch = chunk>>4) ----
#pragma unroll
    for (int c = 0; c < NSTAGES - 1; c++) {
        load_stage(c, c);
        asm volatile("cp.async.commit_group;" ::: "memory");
    }
    int ls = NSTAGES - 1;
    int cs = 0;
    for (int c = 0; c < TOTAL_CHUNKS; c++) {
        asm volatile("cp.async.wait_group %0;" :: "n"(NSTAGES - 2) : "memory");
        __syncthreads();
        if (c + NSTAGES - 1 < TOTAL_CHUNKS) load_stage(c + NSTAGES - 1, ls);
        asm volatile("cp.async.commit_group;" ::: "memory");
        if (++ls == NSTAGES) ls = 0;
        compute_stage(cs);
        if (++cs == NSTAGES) cs = 0;
        if (c == CHUNKS_PER_BRANCH - 1) {
            epilogue(0);
#pragma unroll
            for (int p = 0; p < 4; p++)
#pragma unroll
                for (int j = 0; j < 4; j++)
#pragma unroll
                    for (int d = 0; d < 4; d++) acc[p][j][d] = 0.f;
        }
    }
    epilogue(1);
}

// ======================= fused gate / cell elementwise (x4 vectorized) ==============
__global__ void cell_kernel(const float* __restrict__ cx, float* __restrict__ out,
                            const float* a3, const float* a4, const float* a5,
                            const float* a6, const float* a7, const float* a8,
                            const float* a9, const float* a10, const float* a11) {
    int idx = blockIdx.x * blockDim.x + threadIdx.x;
    if (idx >= B_ * H_ / 4) return;
    int b  = idx >> 8;                 // H_/4 = 256 float4 per row
    int hq = idx & 255;
    const float4* row = (const float4*)&g_part[b][0];
    float4 gi4 = row[hq];
    float4 gj4 = row[hq + 256];
    float4 gf4 = row[hq + 512];
    float4 go4 = row[hq + 768];
    float4 cx4 = ((const float4*)cx)[idx];
    float v3 = *a3, v4 = *a4, v5 = *a5, v6 = *a6, v7 = *a7;
    float v8 = *a8, v9 = *a9, v10 = *a10, v11 = *a11;

    float gi[4] = {gi4.x, gi4.y, gi4.z, gi4.w};
    float gj[4] = {gj4.x, gj4.y, gj4.z, gj4.w};
    float gf[4] = {gf4.x, gf4.y, gf4.z, gf4.w};
    float go[4] = {go4.x, go4.y, go4.z, go4.w};
    float cxv[4] = {cx4.x, cx4.y, cx4.z, cx4.w};
    float nh[4], ncv[4];
#pragma unroll
    for (int j = 0; j < 4; j++) {
        float fg  = qr8(pact_f(sigmoidf_fast(gf[j]), v3), v3);
        float ig  = qr8(pact_f(sigmoidf_fast(gi[j]), v4), v4);
        float act = qr8(pact_f(tanhf_fast(gj[j]),    v5), v5);
        float og  = qr8(pact_f(sigmoidf_fast(go[j]), v6), v6);
        float gc  = qr8(pact_f(cxv[j] * fg,  v7), v7);
        float ai  = qr8(pact_f(ig * act,     v8), v8);
        float nc  = qr8(pact_f(gc + ai,      v9), v9);
        float ac  = qr8(pact_f(tanhf_fast(nc), v10), v10);
        nh[j]  = qr8(pact_f(ac * og, v11), v11);
        ncv[j] = nc;
    }
    ((float4*)out)[idx] = make_float4(nh[0], nh[1], nh[2], nh[3]);
    ((float4*)out)[B_ * H_ / 4 + idx] = make_float4(ncv[0], ncv[1], ncv[2], ncv[3]);
}

// ======================= launch =======================
extern "C" void kernel_launch(void* const* d_in, const int* in_sizes, int n_in,
                              void* d_out, int out_size) {
    const float* input = (const float*)d_in[0];
    const float* hx    = (const float*)d_in[1];
    const float* cx    = (const float*)d_in[2];
    const float* wih   = (const float*)d_in[3];
    const float* whh   = (const float*)d_in[4];
    const float* bih   = (const float*)d_in[5];
    const float* bhh   = (const float*)d_in[6];
    const float* a1    = (const float*)d_in[7];
    const float* a3    = (const float*)d_in[8];
    const float* a4    = (const float*)d_in[9];
    const float* a5    = (const float*)d_in[10];
    const float* a6    = (const float*)d_in[11];
    const float* a7    = (const float*)d_in[12];
    const float* a8    = (const float*)d_in[13];
    const float* a9    = (const float*)d_in[14];
    const float* a10   = (const float*)d_in[15];
    const float* a11   = (const float*)d_in[16];
    float* out = (float*)d_out;

    static int configured = 0;
    if (!configured) {
        cudaFuncSetAttribute(gemm_bf16, cudaFuncAttributeMaxDynamicSharedMemorySize,
                             DSM_BYTES);
        configured = 1;
    }

    prep_kernel<<<16384, 256>>>(input, hx, wih, whh, a1, a11);

    gemm_bf16<<<8192, 128, DSM_BYTES>>>(a1, a11, bih, bhh);

    cell_kernel<<<(B_ * H_ / 4 + 255) / 256, 256>>>(cx, out, a3, a4, a5, a6, a7,
                                                    a8, a9, a10, a11);
}

// round 16
// speedup vs baseline: 1.7943x; 1.0685x over previous
#include <cuda_runtime.h>
#include <cuda_bf16.h>
#include <cstdint>

#define B_   4096
#define K_   1024
#define NG   4096    /* 4*H */
#define H_   1024
#define NM   4

#define STAGE_BYTES 32768     /* A 128x64 bf16 (16KB) + B 128x64 bf16 (16KB) */
#define NSTAGES     3
#define DSM_BYTES   (NSTAGES * STAGE_BYTES)   /* 96 KB -> 2 CTAs/SM */
#define CHUNKS_PER_BRANCH 16
#define TOTAL_CHUNKS      32

// ---- scratch (device globals; no runtime allocation) ----
__device__ __nv_bfloat16 g_yA[2][NM][B_][K_];   // 64 MB  bit-plane ints (bf16), K-major
__device__ __nv_bfloat16 g_Wt[2][NG][K_];       // 16 MB  weight ints, transposed [N][K]
__device__ float         g_part[B_][NG];        // 64 MB  final gates

// ======================= small math helpers =======================
__device__ __forceinline__ float pact_f(float x, float a) {
    float ax = fabsf(x);
    float t  = fabsf(ax - a);
    float s  = (x > 0.f) ? 0.5f : ((x < 0.f) ? -0.5f : 0.f);
    return s * ((ax - t) + a);
}
// fused quantize: qr8(pact(x,a),a) == rint(clip(x*(128/a), +-127)) * (a/128)
// (clamp∘clip = clip; *128 and a∈{1,4} scalings are exact powers of two)
__device__ __forceinline__ float pq(float x, float s1, float s2) {
    float t = x * s1;
    t = fminf(fmaxf(t, -127.f), 127.f);
    return rintf(t) * s2;
}
__device__ __forceinline__ float sigmoidf_fast(float x) { return 1.f / (1.f + __expf(-x)); }
__device__ __forceinline__ float tanhf_fast(float x) {
    return 1.f - 2.f / (__expf(2.f * x) + 1.f);
}

// ======================= PTX helpers (sm_80-class only) =======================
__device__ __forceinline__ uint32_t s2u(const void* p) {
    uint32_t a;
    asm("{ .reg .u64 t; cvta.to.shared.u64 t, %1; cvt.u32.u64 %0, t; }" : "=r"(a) : "l"(p));
    return a;
}
__device__ __forceinline__ void cp16(uint32_t dst, const void* src) {
    asm volatile("cp.async.cg.shared.global [%0], [%1], 16;" :: "r"(dst), "l"(src) : "memory");
}
__device__ __forceinline__ void ldsm4(uint32_t addr, uint32_t& r0, uint32_t& r1,
                                      uint32_t& r2, uint32_t& r3) {
    asm volatile("ldmatrix.sync.aligned.m8n8.x4.shared.b16 {%0,%1,%2,%3}, [%4];"
                 : "=r"(r0), "=r"(r1), "=r"(r2), "=r"(r3) : "r"(addr));
}
__device__ __forceinline__ void hmma(float* d, const uint32_t* a, const uint32_t* b) {
    asm volatile(
        "mma.sync.aligned.m16n8k16.row.col.f32.bf16.bf16.f32 "
        "{%0,%1,%2,%3}, {%4,%5,%6,%7}, {%8,%9}, {%0,%1,%2,%3};"
        : "+f"(d[0]), "+f"(d[1]), "+f"(d[2]), "+f"(d[3])
        : "r"(a[0]), "r"(a[1]), "r"(a[2]), "r"(a[3]), "r"(b[0]), "r"(b[1]));
}

// ======================= fused prep: bit-split + weight quant/transpose ============
__global__ void prep_kernel(const float* __restrict__ input,
                            const float* __restrict__ hx,
                            const float* __restrict__ wih,
                            const float* __restrict__ whh,
                            const float* __restrict__ a1p,
                            const float* __restrict__ a11p) {
    __shared__ float tile[32][33];
    int bx  = blockIdx.x;
    int tid = threadIdx.x;
    if (bx < 8192) {
        // ---- activation bit-split (literal pact kept: feeds exact-int planes) ----
        int idx = bx * 256 + tid;
        int branch = idx >> 20;               // B_*K_/4 = 2^20
        int r      = idx & ((B_ * K_ / 4) - 1);
        float a = branch ? *a11p : *a1p;
        float4 x4 = ((const float4*)(branch ? hx : input))[r];
        float xs[4] = {x4.x, x4.y, x4.z, x4.w};
        unsigned short o[NM][4];
#pragma unroll
        for (int j = 0; j < 4; j++) {
            float xv = pact_f(xs[j], a) / a;
            float beta = 1.f;
#pragma unroll
            for (int mq = 0; mq < NM; mq++) {
                float s = xv / beta;
                s = fminf(fmaxf(s, -0.9921875f), 0.9921875f);
                float yi = rintf(s * 128.f);       // exact int in [-127,127]
                xv = xv - (yi * 0.0078125f) * beta;
                o[mq][j] = __bfloat16_as_ushort(__float2bfloat16(yi));
                beta *= 0.5f;
            }
        }
#pragma unroll
        for (int mq = 0; mq < NM; mq++) {
            uint2 v;
            v.x = (uint32_t)o[mq][0] | ((uint32_t)o[mq][1] << 16);
            v.y = (uint32_t)o[mq][2] | ((uint32_t)o[mq][3] << 16);
            ((uint2*)&g_yA[branch][mq][0][0])[r] = v;
        }
    } else {
        // ---- weight quant + transpose, one 32x32 tile per block ----
        int wb     = bx - 8192;               // 0..8191
        int branch = wb >> 12;                // 4096 tiles per branch
        int rem    = wb & 4095;
        int n0 = (rem & 127) * 32;
        int k0 = (rem >> 7) * 32;
        const float* w = branch ? whh : wih;
        int tx = tid & 31, ty = tid >> 5;     // 32 x 8
#pragma unroll
        for (int i = 0; i < 4; i++)
            tile[ty + i * 8][tx] = w[(size_t)(k0 + ty + i * 8) * NG + n0 + tx];
        __syncthreads();
#pragma unroll
        for (int i = 0; i < 4; i++) {
            float v = tile[tx][ty + i * 8];
            v = fminf(fmaxf(v, -0.9921875f), 0.9921875f);
            g_Wt[branch][n0 + ty + i * 8][k0 + tx] = __float2bfloat16(rintf(v * 128.f));
        }
    }
}

// ======================= bf16 HMMA GEMM, both branches fused =======================
// CHAMPION CONFIG (R9/R10): CTA 128 threads, tile M=128 (4 planes x 32 batch rows)
// x N=128, BK=64, 3-stage cp.async, 96KB dsm -> 2 CTAs/SM. Plane combine in-register,
// direct g_part store/RMW. grid = 4096 swizzled 16x16 groups.
__global__ void __launch_bounds__(128, 2) gemm_bf16(const float* __restrict__ a1p,
                                                    const float* __restrict__ a11p,
                                                    const float* __restrict__ bih,
                                                    const float* __restrict__ bhh) {
    extern __shared__ __align__(128) char dsm[];
    __shared__ float sbias[2][128];

    const int tid  = threadIdx.x;
    const int lane = tid & 31;
    const int warp = tid >> 5;
    const int mh   = warp & 1;     // 16-row half of the 32 batch rows
    const int nq   = warp >> 1;    // 64-col group (0..1)

    // CTA swizzle: 16 groups of (16 blk x 16 n-blocks)
    const int g   = blockIdx.x;
    const int bg  = (g >> 8) & 7;               // blk-group 0..7
    const int ng  = g >> 11;                    // n-group 0..1
    const int rem = g & 255;
    const int blk = bg * 16 + (rem & 15);       // 0..127
    const int n0  = (ng * 16 + (rem >> 4)) * 128;  // 0..3968

    {
        float v0b = fminf(fmaxf(bih[n0 + tid], -0.9921875f), 0.9921875f);
        sbias[0][tid] = rintf(v0b * 128.f);
        float v1b = fminf(fmaxf(bhh[n0 + tid], -0.9921875f), 0.9921875f);
        sbias[1][tid] = rintf(v1b * 128.f);
    }
    const float a1v  = *a1p;
    const float a11v = *a11p;

    const uint32_t smem = s2u(dsm);

    // ---- cp.async slots: 8 A + 8 B 16B-chunks per thread per stage ----
    const int row0 = tid >> 3, ch0 = tid & 7;
    const uint32_t a_src0 = (uint32_t)(((blk * 32 + row0) * K_ + ch0 * 8) * 2);
    const uint32_t a_dst0 = (uint32_t)(row0 * 128 + ((ch0 ^ (row0 & 7)) << 4));
    const uint32_t b_src0 = (uint32_t)(((n0 + row0) * K_ + ch0 * 8) * 2);
    const uint32_t b_dst0 = (uint32_t)(16384 + row0 * 128 + ((ch0 ^ (row0 & 7)) << 4));
    const char* gA = (const char*)&g_yA[0][0][0][0];
    const char* gB = (const char*)&g_Wt[0][0][0];

    // ---- ldmatrix lane constants ----
    const int m   = lane >> 3;
    const int rr  = lane & 7;
    const int akh = m >> 1;             // A: k-half (16B) selector
    const int bkh = m & 1;              // B: k-half selector
    uint32_t aoffx[4];
#pragma unroll
    for (int p = 0; p < 4; p++) {
        int row = p * 32 + mh * 16 + (m & 1) * 8 + rr;
        aoffx[p] = (uint32_t)(row * 128) | ((uint32_t)(row & 7) << 4);
    }
    uint32_t boffx[4];
#pragma unroll
    for (int t = 0; t < 4; t++) {
        int row = nq * 64 + t * 16 + (m >> 1) * 8 + rr;
        boffx[t] = (uint32_t)(16384 + row * 128) | ((uint32_t)(row & 7) << 4);
    }

    float acc[4][8][4];                 // [plane][n8-group][frag]
#pragma unroll
    for (int p = 0; p < 4; p++)
#pragma unroll
        for (int j = 0; j < 8; j++)
#pragma unroll
            for (int d = 0; d < 4; d++) acc[p][j][d] = 0.f;

    auto load_stage = [&](int c, int stage) {
        int br = c >> 4;
        uint32_t k = (uint32_t)(c & 15) * 128;
        uint32_t st = smem + (uint32_t)stage * STAGE_BYTES;
        const char* A  = gA + (size_t)br * ((size_t)NM * B_ * K_ * 2) + k;
        const char* Bp = gB + (size_t)br * ((size_t)NG * K_ * 2) + k;
#pragma unroll
        for (int i = 0; i < 8; i++) {
            cp16(st + a_dst0 + i * 2048,
                 A + a_src0 + (uint32_t)(i >> 1) * (B_ * K_ * 2)
                            + (uint32_t)(i & 1) * (16 * K_ * 2));
            cp16(st + b_dst0 + i * 2048, Bp + b_src0 + (uint32_t)i * (16 * K_ * 2));
        }
    };

    auto compute_stage = [&](int stage) {
        uint32_t st = smem + (uint32_t)stage * STAGE_BYTES;
#pragma unroll
        for (int s = 0; s < 4; s++) {
            uint32_t aks = (uint32_t)(s * 2 + akh) << 4;
            uint32_t bks = (uint32_t)(s * 2 + bkh) << 4;
            uint32_t a[4][4];
#pragma unroll
            for (int p = 0; p < 4; p++)
                ldsm4((st + aoffx[p]) ^ aks, a[p][0], a[p][1], a[p][2], a[p][3]);
#pragma unroll
            for (int t = 0; t < 4; t++) {
                uint32_t b[4];
                ldsm4((st + boffx[t]) ^ bks, b[0], b[1], b[2], b[3]);
#pragma unroll
                for (int p = 0; p < 4; p++) {
                    hmma(acc[p][2 * t],     a[p], &b[0]);
                    hmma(acc[p][2 * t + 1], a[p], &b[2]);
                }
            }
        }
    };

    // plane combine fully in-register -> direct global store/accumulate
    auto epilogue = [&](int br) {
        float av = br ? a11v : a1v;
        float sc0 = av * 0.0078125f;
#pragma unroll
        for (int j = 0; j < 8; j++) {
            int nnb = nq * 64 + j * 8 + (lane & 3) * 2;
#pragma unroll
            for (int d = 0; d < 4; d++) {
                int nn = nnb + (d & 1);
                int rw = mh * 16 + (lane >> 2) + (d >> 1) * 8;
                float bz = sbias[br][nn];
                float v = 0.f;
#pragma unroll
                for (int p = 0; p < 4; p++) {
                    float t = acc[p][j][d] * 0.0078125f + bz;
                    float q = fminf(fmaxf(rintf(t), -127.f), 127.f);
                    v += q * (sc0 / (float)(1 << p));
                }
                float* dst = &g_part[blk * 32 + rw][n0 + nn];
                if (br == 0) *dst = v; else *dst += v;
            }
        }
    };

    // ---- pipeline: 3 stages, 32 chunks (branch = chunk>>4) ----
#pragma unroll
    for (int c = 0; c < NSTAGES - 1; c++) {
        load_stage(c, c);
        asm volatile("cp.async.commit_group;" ::: "memory");
    }
    int ls = NSTAGES - 1;
    int cs = 0;
    for (int c = 0; c < TOTAL_CHUNKS; c++) {
        asm volatile("cp.async.wait_group %0;" :: "n"(NSTAGES - 2) : "memory");
        __syncthreads();
        if (c + NSTAGES - 1 < TOTAL_CHUNKS) load_stage(c + NSTAGES - 1, ls);
        asm volatile("cp.async.commit_group;" ::: "memory");
        if (++ls == NSTAGES) ls = 0;
        compute_stage(cs);
        if (++cs == NSTAGES) cs = 0;
        if (c == CHUNKS_PER_BRANCH - 1) {
            epilogue(0);
#pragma unroll
            for (int p = 0; p < 4; p++)
#pragma unroll
                for (int j = 0; j < 8; j++)
#pragma unroll
                    for (int d = 0; d < 4; d++) acc[p][j][d] = 0.f;
        }
    }
    epilogue(1);
}

// ======================= fused gate / cell elementwise (x4, fused pact+quant) =======
__global__ void cell_kernel(const float* __restrict__ cx, float* __restrict__ out,
                            const float* a3, const float* a4, const float* a5,
                            const float* a6, const float* a7, const float* a8,
                            const float* a9, const float* a10, const float* a11) {
    int idx = blockIdx.x * blockDim.x + threadIdx.x;
    if (idx >= B_ * H_ / 4) return;
    int b  = idx >> 8;                 // H_/4 = 256 float4 per row
    int hq = idx & 255;
    const float4* row = (const float4*)&g_part[b][0];
    float4 gi4 = row[hq];
    float4 gj4 = row[hq + 256];
    float4 gf4 = row[hq + 512];
    float4 go4 = row[hq + 768];
    float4 cx4 = ((const float4*)cx)[idx];

    float v3 = *a3, v4 = *a4, v5 = *a5, v6 = *a6, v7 = *a7;
    float v8 = *a8, v9 = *a9, v10 = *a10, v11 = *a11;
    // fused pact+quant scale pairs: s1 = 128/a, s2 = a/128
    float s13 = 128.f / v3,  s23 = v3 * 0.0078125f;
    float s14 = 128.f / v4,  s24 = v4 * 0.0078125f;
    float s15 = 128.f / v5,  s25 = v5 * 0.0078125f;
    float s16 = 128.f / v6,  s26 = v6 * 0.0078125f;
    float s17 = 128.f / v7,  s27 = v7 * 0.0078125f;
    float s18 = 128.f / v8,  s28 = v8 * 0.0078125f;
    float s19 = 128.f / v9,  s29 = v9 * 0.0078125f;
    float s110 = 128.f / v10, s210 = v10 * 0.0078125f;
    float s111 = 128.f / v11, s211 = v11 * 0.0078125f;

    float gi[4] = {gi4.x, gi4.y, gi4.z, gi4.w};
    float gj[4] = {gj4.x, gj4.y, gj4.z, gj4.w};
    float gf[4] = {gf4.x, gf4.y, gf4.z, gf4.w};
    float go[4] = {go4.x, go4.y, go4.z, go4.w};
    float cxv[4] = {cx4.x, cx4.y, cx4.z, cx4.w};
    float nh[4], ncv[4];
#pragma unroll
    for (int j = 0; j < 4; j++) {
        float fg  = pq(sigmoidf_fast(gf[j]), s13, s23);
        float ig  = pq(sigmoidf_fast(gi[j]), s14, s24);
        float act = pq(tanhf_fast(gj[j]),    s15, s25);
        float og  = pq(sigmoidf_fast(go[j]), s16, s26);
        float gc  = pq(cxv[j] * fg,  s17, s27);
        float ai  = pq(ig * act,     s18, s28);
        float nc  = pq(gc + ai,      s19, s29);
        float ac  = pq(tanhf_fast(nc), s110, s210);
        nh[j]  = pq(ac * og, s111, s211);
        ncv[j] = nc;
    }
    ((float4*)out)[idx] = make_float4(nh[0], nh[1], nh[2], nh[3]);
    ((float4*)out)[B_ * H_ / 4 + idx] = make_float4(ncv[0], ncv[1], ncv[2], ncv[3]);
}

// ======================= launch =======================
extern "C" void kernel_launch(void* const* d_in, const int* in_sizes, int n_in,
                              void* d_out, int out_size) {
    const float* input = (const float*)d_in[0];
    const float* hx    = (const float*)d_in[1];
    const float* cx    = (const float*)d_in[2];
    const float* wih   = (const float*)d_in[3];
    const float* whh   = (const float*)d_in[4];
    const float* bih   = (const float*)d_in[5];
    const float* bhh   = (const float*)d_in[6];
    const float* a1    = (const float*)d_in[7];
    const float* a3    = (const float*)d_in[8];
    const float* a4    = (const float*)d_in[9];
    const float* a5    = (const float*)d_in[10];
    const float* a6    = (const float*)d_in[11];
    const float* a7    = (const float*)d_in[12];
    const float* a8    = (const float*)d_in[13];
    const float* a9    = (const float*)d_in[14];
    const float* a10   = (const float*)d_in[15];
    const float* a11   = (const float*)d_in[16];
    float* out = (float*)d_out;

    static int configured = 0;
    if (!configured) {
        cudaFuncSetAttribute(gemm_bf16, cudaFuncAttributeMaxDynamicSharedMemorySize,
                             DSM_BYTES);
        configured = 1;
    }

    prep_kernel<<<16384, 256>>>(input, hx, wih, whh, a1, a11);

    gemm_bf16<<<4096, 128, DSM_BYTES>>>(a1, a11, bih, bhh);

    cell_kernel<<<(B_ * H_ / 4 + 255) / 256, 256>>>(cx, out, a3, a4, a5, a6, a7,
                                                    a8, a9, a10, a11);
}